// round 16
// baseline (speedup 1.0000x reference)
#include <cuda_runtime.h>
#include <cstdint>
#include <math.h>

#define NN    50000
#define EE    400000
#define ETOT  (NN + EE)
#define CH    256
#define KIN   20
#define NEG_SLOPE 0.2f
#define EPSS  1e-16f

// ---------------- scratch (static device globals; no allocations) ----------
__device__ float g_xl1[NN * CH];
__device__ float g_xr1[NN * CH];
__device__ float g_h[NN * CH];
__device__ float g_xl2[NN * CH];
__device__ float g_xr2[NN * CH];
__device__ int   g_deg[NN];
__device__ int   g_off[NN + 1];
__device__ int   g_part[64];
__device__ int   g_csr_src[ETOT];

__device__ __forceinline__ float lrelu(float v) {
    return v > 0.0f ? v : NEG_SLOPE * v;
}

// ---- packed f32x2 (FFMA2) helpers ----
__device__ __forceinline__ unsigned long long pack2(float lo, float hi) {
    unsigned long long r;
    asm("mov.b64 %0, {%1, %2};" : "=l"(r) : "f"(lo), "f"(hi));
    return r;
}
__device__ __forceinline__ unsigned long long fma2(unsigned long long a,
                                                   unsigned long long b,
                                                   unsigned long long c) {
    unsigned long long d;
    asm("fma.rn.f32x2 %0, %1, %2, %3;" : "=l"(d) : "l"(a), "l"(b), "l"(c));
    return d;
}
__device__ __forceinline__ float2 unpack2(unsigned long long v) {
    float lo, hi;
    asm("mov.b64 {%0, %1}, %2;" : "=f"(lo), "=f"(hi) : "l"(v));
    return make_float2(lo, hi);
}

// ================= CSR construction =================
__global__ void zero_deg() {
    int i = blockIdx.x * blockDim.x + threadIdx.x;
    if (i < NN) g_deg[i] = 0;
}

__global__ void csr_count(const int* __restrict__ ei) {
    int e = blockIdx.x * blockDim.x + threadIdx.x;
    if (e >= ETOT) return;
    int dst = (e < EE) ? ei[EE + e] : e - EE;
    atomicAdd(&g_deg[dst], 1);
}

__global__ void scan1() {
    int tid = threadIdx.x;
    int lane = tid & 31, wid = tid >> 5;
    __shared__ int wsum[32];
    int i = blockIdx.x * 1024 + tid;
    int v = (i < NN) ? g_deg[i] : 0;
    if (i < NN) g_deg[i] = 0;
    int x = v;
    #pragma unroll
    for (int o = 1; o < 32; o <<= 1) {
        int y = __shfl_up_sync(0xffffffffu, x, o);
        if (lane >= o) x += y;
    }
    if (lane == 31) wsum[wid] = x;
    __syncthreads();
    if (wid == 0) {
        int w = wsum[lane];
        #pragma unroll
        for (int o = 1; o < 32; o <<= 1) {
            int y = __shfl_up_sync(0xffffffffu, w, o);
            if (lane >= o) w += y;
        }
        wsum[lane] = w;
    }
    __syncthreads();
    int incl = x + (wid > 0 ? wsum[wid - 1] : 0);
    if (i < NN) g_off[i] = incl - v;
    if (tid == 1023) g_part[blockIdx.x] = incl;
}

__global__ void scan2(int nblk) {
    __shared__ int sp[64];
    int t = threadIdx.x;
    sp[t] = (t < nblk) ? g_part[t] : 0;
    __syncthreads();
    if (t == 0) {
        int run = 0;
        for (int i = 0; i < nblk; i++) { int tmp = sp[i]; sp[i] = run; run += tmp; }
    }
    __syncthreads();
    if (t < nblk) g_part[t] = sp[t];
}

__global__ void scan3() {
    int i = blockIdx.x * 1024 + threadIdx.x;
    if (i < NN) g_off[i] += g_part[blockIdx.x];
    if (i == 0) g_off[NN] = ETOT;
}

__global__ void csr_scatter(const int* __restrict__ ei) {
    int e = blockIdx.x * blockDim.x + threadIdx.x;
    if (e >= ETOT) return;
    int src, dst;
    if (e < EE) { src = ei[e]; dst = ei[EE + e]; }
    else        { src = dst = e - EE; }
    int pos = g_off[dst] + atomicAdd(&g_deg[dst], 1);
    g_csr_src[pos] = src;
}

// ================= layer-1 GEMM: x[N,20]@W[20,256]+b, 64 rows/block ========
__global__ void gemm1_kernel(const float* __restrict__ x,
                             const float* __restrict__ Wl, const float* __restrict__ bl,
                             const float* __restrict__ Wr, const float* __restrict__ br) {
    __shared__ float swl[KIN * 256];
    __shared__ float swr[KIN * 256];
    __shared__ float sx[64][KIN];
    int tid = threadIdx.x;
    for (int i = tid; i < KIN * 256; i += 256) { swl[i] = Wl[i]; swr[i] = Wr[i]; }
    int nb = blockIdx.x * 64;
    for (int i = tid; i < 64 * KIN; i += 256) {
        int node = nb + i / KIN;
        sx[i / KIN][i % KIN] = (node < NN) ? x[node * KIN + (i % KIN)] : 0.0f;
    }
    __syncthreads();
    float bL = bl[tid], bR = br[tid];
    #pragma unroll 4
    for (int i = 0; i < 64; i++) {
        int node = nb + i;
        if (node >= NN) break;
        float al = bL, ar = bR;
        #pragma unroll
        for (int k = 0; k < KIN; k++) {
            float xv = sx[i][k];
            al = fmaf(xv, swl[k * 256 + tid], al);
            ar = fmaf(xv, swr[k * 256 + tid], ar);
        }
        g_xl1[node * 256 + tid] = al;
        g_xr1[node * 256 + tid] = ar;
    }
}

// ================= dual layer-2 GEMM, 128x64 tile, 8x4x2 per thread =========
__global__ void __launch_bounds__(256, 2)
gemm_dual(const float* __restrict__ Wl, const float* __restrict__ bl,
          const float* __restrict__ Wr, const float* __restrict__ br) {
    const float* __restrict__ A = g_h;
    __shared__ float As[16][128];
    __shared__ float Bl[16][64];
    __shared__ float Br[16][64];
    int tid = threadIdx.x;
    int tx = tid & 15;
    int ty = tid >> 4;
    int row0 = blockIdx.x * 128;
    int col0 = blockIdx.y * 64;

    unsigned long long accL[8][2], accR[8][2];
    #pragma unroll
    for (int i = 0; i < 8; i++) {
        accL[i][0] = 0ull; accL[i][1] = 0ull;
        accR[i][0] = 0ull; accR[i][1] = 0ull;
    }

    for (int kt = 0; kt < 256; kt += 16) {
        #pragma unroll
        for (int j = 0; j < 8; j++) {
            int i = tid + j * 256;
            int m = i >> 4, k = i & 15;
            int row = row0 + m;
            As[k][m] = (row < NN) ? A[row * 256 + kt + k] : 0.0f;
        }
        #pragma unroll
        for (int j = 0; j < 4; j++) {
            int i = tid + j * 256;
            int k = i >> 6, col = i & 63;
            Bl[k][col] = Wl[(kt + k) * 256 + col0 + col];
            Br[k][col] = Wr[(kt + k) * 256 + col0 + col];
        }
        __syncthreads();
        #pragma unroll
        for (int k = 0; k < 16; k++) {
            float4 a0 = *(const float4*)&As[k][ty * 8];
            float4 a1 = *(const float4*)&As[k][ty * 8 + 4];
            ulonglong2 b  = *(const ulonglong2*)&Bl[k][tx * 4];
            ulonglong2 b2 = *(const ulonglong2*)&Br[k][tx * 4];
            unsigned long long ap[8];
            ap[0] = pack2(a0.x, a0.x); ap[1] = pack2(a0.y, a0.y);
            ap[2] = pack2(a0.z, a0.z); ap[3] = pack2(a0.w, a0.w);
            ap[4] = pack2(a1.x, a1.x); ap[5] = pack2(a1.y, a1.y);
            ap[6] = pack2(a1.z, a1.z); ap[7] = pack2(a1.w, a1.w);
            #pragma unroll
            for (int i = 0; i < 8; i++) {
                accL[i][0] = fma2(ap[i], b.x,  accL[i][0]);
                accL[i][1] = fma2(ap[i], b.y,  accL[i][1]);
                accR[i][0] = fma2(ap[i], b2.x, accR[i][0]);
                accR[i][1] = fma2(ap[i], b2.y, accR[i][1]);
            }
        }
        __syncthreads();
    }
    #pragma unroll
    for (int i = 0; i < 8; i++) {
        int row = row0 + ty * 8 + i;
        if (row >= NN) continue;
        int col = col0 + tx * 4;
        float2 l0 = unpack2(accL[i][0]), l1 = unpack2(accL[i][1]);
        float2 r0 = unpack2(accR[i][0]), r1 = unpack2(accR[i][1]);
        float4 vl, vr;
        vl.x = l0.x + bl[col + 0]; vl.y = l0.y + bl[col + 1];
        vl.z = l1.x + bl[col + 2]; vl.w = l1.y + bl[col + 3];
        vr.x = r0.x + br[col + 0]; vr.y = r0.y + br[col + 1];
        vr.z = r1.x + br[col + 2]; vr.w = r1.y + br[col + 3];
        *(float4*)&g_xl2[row * 256 + col] = vl;
        *(float4*)&g_xr2[row * 256 + col] = vr;
    }
}

// ================= fused edge pass: 2 independent nodes per warp ============
// Warp processes nodes 2w and 2w+1 with interleaved, fully independent
// online-softmax chains (true ILP x2, no merge). Lane owns 8 channels.
template<int LAYER>
__global__ void fused_edge(const float* __restrict__ att,
                           const float* __restrict__ bias,
                           float* __restrict__ out_arg) {
    const float* __restrict__ xl = (LAYER == 1) ? g_xl1 : g_xl2;
    const float* __restrict__ xr = (LAYER == 1) ? g_xr1 : g_xr2;

    int gw = (blockIdx.x * blockDim.x + threadIdx.x) >> 5;
    int lane = threadIdx.x & 31;
    int n0 = gw * 2, n1 = gw * 2 + 1;
    if (n0 >= NN) return;
    bool has1 = (n1 < NN);
    int c = lane * 8;

    // per-node resident data
    const float4* pr0 = (const float4*)(xr + n0 * CH + c);
    float4 R0a = pr0[0], R0b = pr0[1];
    float4 R1a = make_float4(0.f,0.f,0.f,0.f), R1b = R1a;
    if (has1) {
        const float4* pr1 = (const float4*)(xr + n1 * CH + c);
        R1a = pr1[0]; R1b = pr1[1];
    }
    const float4* pa = (const float4*)(att + c);
    float4 w0 = pa[0], w1 = pa[1];

    int s0 = g_off[n0], e0 = g_off[n0 + 1];
    int s1 = has1 ? g_off[n1] : 0, e1 = has1 ? g_off[n1 + 1] : 0;

    float m0 = -INFINITY, sum0 = 0.0f;
    float m1 = -INFINITY, sum1 = 0.0f;
    float4 acc0a = make_float4(0.f,0.f,0.f,0.f), acc0b = acc0a;
    float4 acc1a = acc0a, acc1b = acc0a;

    // 1-deep prefetch per chain
    float4 A0a, A0b, A1a, A1b;
    if (s0 < e0) {
        const float4* p = (const float4*)(xl + g_csr_src[s0] * CH + c);
        A0a = p[0]; A0b = p[1];
    }
    if (s1 < e1) {
        const float4* p = (const float4*)(xl + g_csr_src[s1] * CH + c);
        A1a = p[0]; A1b = p[1];
    }

    while (s0 < e0 || s1 < e1) {
        bool a0 = (s0 < e0), a1 = (s1 < e1);
        float4 C0a = A0a, C0b = A0b, C1a = A1a, C1b = A1b;
        // prefetch next edge per chain
        if (s0 + 1 < e0) {
            const float4* p = (const float4*)(xl + g_csr_src[s0 + 1] * CH + c);
            A0a = p[0]; A0b = p[1];
        }
        if (s1 + 1 < e1) {
            const float4* p = (const float4*)(xl + g_csr_src[s1 + 1] * CH + c);
            A1a = p[0]; A1b = p[1];
        }
        // two independent logit chains
        float p0, p1;
        p0  =        w0.x * lrelu(C0a.x + R0a.x);
        p1  =        w0.x * lrelu(C1a.x + R1a.x);
        p0 = fmaf(w0.y, lrelu(C0a.y + R0a.y), p0);
        p1 = fmaf(w0.y, lrelu(C1a.y + R1a.y), p1);
        p0 = fmaf(w0.z, lrelu(C0a.z + R0a.z), p0);
        p1 = fmaf(w0.z, lrelu(C1a.z + R1a.z), p1);
        p0 = fmaf(w0.w, lrelu(C0a.w + R0a.w), p0);
        p1 = fmaf(w0.w, lrelu(C1a.w + R1a.w), p1);
        p0 = fmaf(w1.x, lrelu(C0b.x + R0b.x), p0);
        p1 = fmaf(w1.x, lrelu(C1b.x + R1b.x), p1);
        p0 = fmaf(w1.y, lrelu(C0b.y + R0b.y), p0);
        p1 = fmaf(w1.y, lrelu(C1b.y + R1b.y), p1);
        p0 = fmaf(w1.z, lrelu(C0b.z + R0b.z), p0);
        p1 = fmaf(w1.z, lrelu(C1b.z + R1b.z), p1);
        p0 = fmaf(w1.w, lrelu(C0b.w + R0b.w), p0);
        p1 = fmaf(w1.w, lrelu(C1b.w + R1b.w), p1);
        // interleaved shuffle reductions (full warp executes)
        if (LAYER == 1) {
            p0 += __shfl_xor_sync(0xffffffffu, p0, 4);
            p1 += __shfl_xor_sync(0xffffffffu, p1, 4);
            p0 += __shfl_xor_sync(0xffffffffu, p0, 2);
            p1 += __shfl_xor_sync(0xffffffffu, p1, 2);
            p0 += __shfl_xor_sync(0xffffffffu, p0, 1);
            p1 += __shfl_xor_sync(0xffffffffu, p1, 1);
        } else {
            #pragma unroll
            for (int off = 16; off > 0; off >>= 1) {
                p0 += __shfl_xor_sync(0xffffffffu, p0, off);
                p1 += __shfl_xor_sync(0xffffffffu, p1, off);
            }
        }
        // chain-0 update
        if (a0) {
            if (p0 > m0) {
                float sc = __expf(m0 - p0);
                sum0 *= sc;
                acc0a.x *= sc; acc0a.y *= sc; acc0a.z *= sc; acc0a.w *= sc;
                acc0b.x *= sc; acc0b.y *= sc; acc0b.z *= sc; acc0b.w *= sc;
                m0 = p0;
            }
            float wj = __expf(p0 - m0);
            sum0 += wj;
            acc0a.x = fmaf(wj, C0a.x, acc0a.x); acc0a.y = fmaf(wj, C0a.y, acc0a.y);
            acc0a.z = fmaf(wj, C0a.z, acc0a.z); acc0a.w = fmaf(wj, C0a.w, acc0a.w);
            acc0b.x = fmaf(wj, C0b.x, acc0b.x); acc0b.y = fmaf(wj, C0b.y, acc0b.y);
            acc0b.z = fmaf(wj, C0b.z, acc0b.z); acc0b.w = fmaf(wj, C0b.w, acc0b.w);
            s0++;
        }
        // chain-1 update
        if (a1) {
            if (p1 > m1) {
                float sc = __expf(m1 - p1);
                sum1 *= sc;
                acc1a.x *= sc; acc1a.y *= sc; acc1a.z *= sc; acc1a.w *= sc;
                acc1b.x *= sc; acc1b.y *= sc; acc1b.z *= sc; acc1b.w *= sc;
                m1 = p1;
            }
            float wj = __expf(p1 - m1);
            sum1 += wj;
            acc1a.x = fmaf(wj, C1a.x, acc1a.x); acc1a.y = fmaf(wj, C1a.y, acc1a.y);
            acc1a.z = fmaf(wj, C1a.z, acc1a.z); acc1a.w = fmaf(wj, C1a.w, acc1a.w);
            acc1b.x = fmaf(wj, C1b.x, acc1b.x); acc1b.y = fmaf(wj, C1b.y, acc1b.y);
            acc1b.z = fmaf(wj, C1b.z, acc1b.z); acc1b.w = fmaf(wj, C1b.w, acc1b.w);
            s1++;
        }
    }

    const float4* pb = (const float4*)(bias + c);
    float4 b0 = pb[0], b1 = pb[1];
    float* outp = (LAYER == 1) ? g_h : out_arg;

    {   // node n0 epilogue
        float inv = 1.0f / (sum0 + EPSS);
        float v[8] = { acc0a.x * inv + b0.x, acc0a.y * inv + b0.y,
                       acc0a.z * inv + b0.z, acc0a.w * inv + b0.w,
                       acc0b.x * inv + b1.x, acc0b.y * inv + b1.y,
                       acc0b.z * inv + b1.z, acc0b.w * inv + b1.w };
        if (LAYER == 1) {
            #pragma unroll
            for (int j = 0; j < 8; j++) v[j] = v[j] > 0.0f ? v[j] : expm1f(v[j]);
        }
        float4* po = (float4*)(outp + n0 * CH + c);
        po[0] = make_float4(v[0], v[1], v[2], v[3]);
        po[1] = make_float4(v[4], v[5], v[6], v[7]);
    }
    if (has1) {   // node n1 epilogue
        float inv = 1.0f / (sum1 + EPSS);
        float v[8] = { acc1a.x * inv + b0.x, acc1a.y * inv + b0.y,
                       acc1a.z * inv + b0.z, acc1a.w * inv + b0.w,
                       acc1b.x * inv + b1.x, acc1b.y * inv + b1.y,
                       acc1b.z * inv + b1.z, acc1b.w * inv + b1.w };
        if (LAYER == 1) {
            #pragma unroll
            for (int j = 0; j < 8; j++) v[j] = v[j] > 0.0f ? v[j] : expm1f(v[j]);
        }
        float4* po = (float4*)(outp + n1 * CH + c);
        po[0] = make_float4(v[0], v[1], v[2], v[3]);
        po[1] = make_float4(v[4], v[5], v[6], v[7]);
    }
}

// ================= launcher =================================================
extern "C" void kernel_launch(void* const* d_in, const int* in_sizes, int n_in,
                              void* d_out, int out_size) {
    const float* x     = (const float*)d_in[0];
    const int*   ei    = (const int*)  d_in[1];
    const float* W_l1  = (const float*)d_in[2];
    const float* b_l1  = (const float*)d_in[3];
    const float* W_r1  = (const float*)d_in[4];
    const float* b_r1  = (const float*)d_in[5];
    const float* att1  = (const float*)d_in[6];
    const float* bias1 = (const float*)d_in[7];
    const float* W_l2  = (const float*)d_in[8];
    const float* b_l2  = (const float*)d_in[9];
    const float* W_r2  = (const float*)d_in[10];
    const float* b_r2  = (const float*)d_in[11];
    const float* att2  = (const float*)d_in[12];
    const float* bias2 = (const float*)d_in[13];
    float* out = (float*)d_out;

    const int T = 256;
    int blkN    = (NN + T - 1) / T;
    int blkE    = (ETOT + T - 1) / T;
    int nPairWarps = (NN + 1) / 2;                 // 25000
    int blkNode = (nPairWarps + 7) / 8;            // 8 warps/block
    int blkG1   = (NN + 63) / 64;
    int blkScan = (NN + 1023) / 1024;  // 49

    // one-time side-stream + events (host resources only; no device memory)
    static cudaStream_t s2 = nullptr;
    static cudaEvent_t evFork = nullptr, evJoin = nullptr;
    if (s2 == nullptr) {
        cudaStreamCreateWithFlags(&s2, cudaStreamNonBlocking);
        cudaEventCreateWithFlags(&evFork, cudaEventDisableTiming);
        cudaEventCreateWithFlags(&evJoin, cudaEventDisableTiming);
    }

    // fork: CSR build on s2, concurrent with gemm1 on the main stream
    cudaEventRecord(evFork, 0);
    cudaStreamWaitEvent(s2, evFork, 0);

    zero_deg<<<blkN, T, 0, s2>>>();
    csr_count<<<blkE, T, 0, s2>>>(ei);
    scan1<<<blkScan, 1024, 0, s2>>>();
    scan2<<<1, 64, 0, s2>>>(blkScan);
    scan3<<<blkScan, 1024, 0, s2>>>();
    csr_scatter<<<blkE, T, 0, s2>>>(ei);
    cudaEventRecord(evJoin, s2);

    // main stream: layer-1 GEMM (independent of CSR)
    gemm1_kernel<<<blkG1, T>>>(x, W_l1, b_l1, W_r1, b_r1);

    // join: fused edge pass needs both CSR and gemm1
    cudaStreamWaitEvent(0, evJoin, 0);
    fused_edge<1><<<blkNode, T>>>(att1, bias1, nullptr);

    // layer 2
    dim3 g2((NN + 127) / 128, 4);
    gemm_dual<<<g2, T>>>(W_l2, b_l2, W_r2, b_r2);
    fused_edge<2><<<blkNode, T>>>(att2, bias2, out);
}

// round 17
// speedup vs baseline: 1.0626x; 1.0626x over previous
#include <cuda_runtime.h>
#include <cstdint>
#include <math.h>

#define NN    50000
#define EE    400000
#define ETOT  (NN + EE)
#define CH    256
#define KIN   20
#define NEG_SLOPE 0.2f
#define EPSS  1e-16f
#define SPLIT 25088          // node/row pipeline split (multiple of 128)

// ---------------- scratch (static device globals; no allocations) ----------
__device__ float g_xl1[NN * CH];
__device__ float g_xr1[NN * CH];
__device__ float g_h[NN * CH];
__device__ float g_xl2[NN * CH];
__device__ float g_xr2[NN * CH];
__device__ int   g_deg[NN];
__device__ int   g_off[NN + 1];
__device__ int   g_part[64];
__device__ int   g_csr_src[ETOT];

__device__ __forceinline__ float lrelu(float v) {
    return v > 0.0f ? v : NEG_SLOPE * v;
}

// ---- packed f32x2 (FFMA2) helpers ----
__device__ __forceinline__ unsigned long long pack2(float lo, float hi) {
    unsigned long long r;
    asm("mov.b64 %0, {%1, %2};" : "=l"(r) : "f"(lo), "f"(hi));
    return r;
}
__device__ __forceinline__ unsigned long long fma2(unsigned long long a,
                                                   unsigned long long b,
                                                   unsigned long long c) {
    unsigned long long d;
    asm("fma.rn.f32x2 %0, %1, %2, %3;" : "=l"(d) : "l"(a), "l"(b), "l"(c));
    return d;
}
__device__ __forceinline__ float2 unpack2(unsigned long long v) {
    float lo, hi;
    asm("mov.b64 {%0, %1}, %2;" : "=f"(lo), "=f"(hi) : "l"(v));
    return make_float2(lo, hi);
}

// ================= CSR construction =================
__global__ void zero_deg() {
    int i = blockIdx.x * blockDim.x + threadIdx.x;
    if (i < NN) g_deg[i] = 0;
}

__global__ void csr_count(const int* __restrict__ ei) {
    int e = blockIdx.x * blockDim.x + threadIdx.x;
    if (e >= ETOT) return;
    int dst = (e < EE) ? ei[EE + e] : e - EE;
    atomicAdd(&g_deg[dst], 1);
}

__global__ void scan1() {
    int tid = threadIdx.x;
    int lane = tid & 31, wid = tid >> 5;
    __shared__ int wsum[32];
    int i = blockIdx.x * 1024 + tid;
    int v = (i < NN) ? g_deg[i] : 0;
    if (i < NN) g_deg[i] = 0;
    int x = v;
    #pragma unroll
    for (int o = 1; o < 32; o <<= 1) {
        int y = __shfl_up_sync(0xffffffffu, x, o);
        if (lane >= o) x += y;
    }
    if (lane == 31) wsum[wid] = x;
    __syncthreads();
    if (wid == 0) {
        int w = wsum[lane];
        #pragma unroll
        for (int o = 1; o < 32; o <<= 1) {
            int y = __shfl_up_sync(0xffffffffu, w, o);
            if (lane >= o) w += y;
        }
        wsum[lane] = w;
    }
    __syncthreads();
    int incl = x + (wid > 0 ? wsum[wid - 1] : 0);
    if (i < NN) g_off[i] = incl - v;
    if (tid == 1023) g_part[blockIdx.x] = incl;
}

__global__ void scan2(int nblk) {
    __shared__ int sp[64];
    int t = threadIdx.x;
    sp[t] = (t < nblk) ? g_part[t] : 0;
    __syncthreads();
    if (t == 0) {
        int run = 0;
        for (int i = 0; i < nblk; i++) { int tmp = sp[i]; sp[i] = run; run += tmp; }
    }
    __syncthreads();
    if (t < nblk) g_part[t] = sp[t];
}

__global__ void scan3() {
    int i = blockIdx.x * 1024 + threadIdx.x;
    if (i < NN) g_off[i] += g_part[blockIdx.x];
    if (i == 0) g_off[NN] = ETOT;
}

__global__ void csr_scatter(const int* __restrict__ ei) {
    int e = blockIdx.x * blockDim.x + threadIdx.x;
    if (e >= ETOT) return;
    int src, dst;
    if (e < EE) { src = ei[e]; dst = ei[EE + e]; }
    else        { src = dst = e - EE; }
    int pos = g_off[dst] + atomicAdd(&g_deg[dst], 1);
    g_csr_src[pos] = src;
}

// ================= layer-1 GEMM: x[N,20]@W[20,256]+b, 64 rows/block ========
__global__ void gemm1_kernel(const float* __restrict__ x,
                             const float* __restrict__ Wl, const float* __restrict__ bl,
                             const float* __restrict__ Wr, const float* __restrict__ br) {
    __shared__ float swl[KIN * 256];
    __shared__ float swr[KIN * 256];
    __shared__ float sx[64][KIN];
    int tid = threadIdx.x;
    for (int i = tid; i < KIN * 256; i += 256) { swl[i] = Wl[i]; swr[i] = Wr[i]; }
    int nb = blockIdx.x * 64;
    for (int i = tid; i < 64 * KIN; i += 256) {
        int node = nb + i / KIN;
        sx[i / KIN][i % KIN] = (node < NN) ? x[node * KIN + (i % KIN)] : 0.0f;
    }
    __syncthreads();
    float bL = bl[tid], bR = br[tid];
    #pragma unroll 4
    for (int i = 0; i < 64; i++) {
        int node = nb + i;
        if (node >= NN) break;
        float al = bL, ar = bR;
        #pragma unroll
        for (int k = 0; k < KIN; k++) {
            float xv = sx[i][k];
            al = fmaf(xv, swl[k * 256 + tid], al);
            ar = fmaf(xv, swr[k * 256 + tid], ar);
        }
        g_xl1[node * 256 + tid] = al;
        g_xr1[node * 256 + tid] = ar;
    }
}

// ================= dual layer-2 GEMM, 128x64 tile, 8x4x2 per thread =========
// rowBase: starting row of this launch's tile range.
__global__ void __launch_bounds__(256, 2)
gemm_dual(const float* __restrict__ Wl, const float* __restrict__ bl,
          const float* __restrict__ Wr, const float* __restrict__ br,
          int rowBase) {
    const float* __restrict__ A = g_h;
    __shared__ float As[16][128];
    __shared__ float Bl[16][64];
    __shared__ float Br[16][64];
    int tid = threadIdx.x;
    int tx = tid & 15;
    int ty = tid >> 4;
    int row0 = rowBase + blockIdx.x * 128;
    int col0 = blockIdx.y * 64;

    unsigned long long accL[8][2], accR[8][2];
    #pragma unroll
    for (int i = 0; i < 8; i++) {
        accL[i][0] = 0ull; accL[i][1] = 0ull;
        accR[i][0] = 0ull; accR[i][1] = 0ull;
    }

    for (int kt = 0; kt < 256; kt += 16) {
        #pragma unroll
        for (int j = 0; j < 8; j++) {
            int i = tid + j * 256;
            int m = i >> 4, k = i & 15;
            int row = row0 + m;
            As[k][m] = (row < NN) ? A[row * 256 + kt + k] : 0.0f;
        }
        #pragma unroll
        for (int j = 0; j < 4; j++) {
            int i = tid + j * 256;
            int k = i >> 6, col = i & 63;
            Bl[k][col] = Wl[(kt + k) * 256 + col0 + col];
            Br[k][col] = Wr[(kt + k) * 256 + col0 + col];
        }
        __syncthreads();
        #pragma unroll
        for (int k = 0; k < 16; k++) {
            float4 a0 = *(const float4*)&As[k][ty * 8];
            float4 a1 = *(const float4*)&As[k][ty * 8 + 4];
            ulonglong2 b  = *(const ulonglong2*)&Bl[k][tx * 4];
            ulonglong2 b2 = *(const ulonglong2*)&Br[k][tx * 4];
            unsigned long long ap[8];
            ap[0] = pack2(a0.x, a0.x); ap[1] = pack2(a0.y, a0.y);
            ap[2] = pack2(a0.z, a0.z); ap[3] = pack2(a0.w, a0.w);
            ap[4] = pack2(a1.x, a1.x); ap[5] = pack2(a1.y, a1.y);
            ap[6] = pack2(a1.z, a1.z); ap[7] = pack2(a1.w, a1.w);
            #pragma unroll
            for (int i = 0; i < 8; i++) {
                accL[i][0] = fma2(ap[i], b.x,  accL[i][0]);
                accL[i][1] = fma2(ap[i], b.y,  accL[i][1]);
                accR[i][0] = fma2(ap[i], b2.x, accR[i][0]);
                accR[i][1] = fma2(ap[i], b2.y, accR[i][1]);
            }
        }
        __syncthreads();
    }
    #pragma unroll
    for (int i = 0; i < 8; i++) {
        int row = row0 + ty * 8 + i;
        if (row >= NN) continue;
        int col = col0 + tx * 4;
        float2 l0 = unpack2(accL[i][0]), l1 = unpack2(accL[i][1]);
        float2 r0 = unpack2(accR[i][0]), r1 = unpack2(accR[i][1]);
        float4 vl, vr;
        vl.x = l0.x + bl[col + 0]; vl.y = l0.y + bl[col + 1];
        vl.z = l1.x + bl[col + 2]; vl.w = l1.y + bl[col + 3];
        vr.x = r0.x + br[col + 0]; vr.y = r0.y + br[col + 1];
        vr.z = r1.x + br[col + 2]; vr.w = r1.y + br[col + 3];
        *(float4*)&g_xl2[row * 256 + col] = vl;
        *(float4*)&g_xr2[row * 256 + col] = vr;
    }
}

// ================= fused edge pass (R7 shape) over node range ===============
template<int LAYER>
__global__ void fused_edge(const float* __restrict__ att,
                           const float* __restrict__ bias,
                           float* __restrict__ out_arg,
                           int nbase, int ncount) {
    const float* __restrict__ xl = (LAYER == 1) ? g_xl1 : g_xl2;
    const float* __restrict__ xr = (LAYER == 1) ? g_xr1 : g_xr2;

    int idx = (blockIdx.x * blockDim.x + threadIdx.x) >> 5;
    int lane = threadIdx.x & 31;
    if (idx >= ncount) return;
    int node = nbase + idx;
    int s0 = g_off[node], s1 = g_off[node + 1];
    int c = lane * 8;

    const float4* pr = (const float4*)(xr + node * CH + c);
    float4 r0 = pr[0], r1 = pr[1];
    const float4* pa = (const float4*)(att + c);
    float4 w0 = pa[0], w1 = pa[1];

    float m = -INFINITY, ssum = 0.0f;
    float4 acc0 = make_float4(0.f, 0.f, 0.f, 0.f);
    float4 acc1 = make_float4(0.f, 0.f, 0.f, 0.f);

    float4 A0, A1, B0, B1;
    {
        const float4* p = (const float4*)(xl + g_csr_src[s0] * CH + c);
        A0 = p[0]; A1 = p[1];
    }
    if (s0 + 1 < s1) {
        const float4* p = (const float4*)(xl + g_csr_src[s0 + 1] * CH + c);
        B0 = p[0]; B1 = p[1];
    }

    int s = s0;
    for (; s + 1 < s1; s += 2) {
        float4 c0 = A0, c1 = A1, d0 = B0, d1 = B1;
        if (s + 2 < s1) {
            const float4* p = (const float4*)(xl + g_csr_src[s + 2] * CH + c);
            A0 = p[0]; A1 = p[1];
        }
        if (s + 3 < s1) {
            const float4* p = (const float4*)(xl + g_csr_src[s + 3] * CH + c);
            B0 = p[0]; B1 = p[1];
        }
        float p1, p2;
        p1  =        w0.x * lrelu(c0.x + r0.x);
        p2  =        w0.x * lrelu(d0.x + r0.x);
        p1 = fmaf(w0.y, lrelu(c0.y + r0.y), p1);
        p2 = fmaf(w0.y, lrelu(d0.y + r0.y), p2);
        p1 = fmaf(w0.z, lrelu(c0.z + r0.z), p1);
        p2 = fmaf(w0.z, lrelu(d0.z + r0.z), p2);
        p1 = fmaf(w0.w, lrelu(c0.w + r0.w), p1);
        p2 = fmaf(w0.w, lrelu(d0.w + r0.w), p2);
        p1 = fmaf(w1.x, lrelu(c1.x + r1.x), p1);
        p2 = fmaf(w1.x, lrelu(d1.x + r1.x), p2);
        p1 = fmaf(w1.y, lrelu(c1.y + r1.y), p1);
        p2 = fmaf(w1.y, lrelu(d1.y + r1.y), p2);
        p1 = fmaf(w1.z, lrelu(c1.z + r1.z), p1);
        p2 = fmaf(w1.z, lrelu(d1.z + r1.z), p2);
        p1 = fmaf(w1.w, lrelu(c1.w + r1.w), p1);
        p2 = fmaf(w1.w, lrelu(d1.w + r1.w), p2);
        if (LAYER == 1) {
            p1 += __shfl_xor_sync(0xffffffffu, p1, 4);
            p2 += __shfl_xor_sync(0xffffffffu, p2, 4);
            p1 += __shfl_xor_sync(0xffffffffu, p1, 2);
            p2 += __shfl_xor_sync(0xffffffffu, p2, 2);
            p1 += __shfl_xor_sync(0xffffffffu, p1, 1);
            p2 += __shfl_xor_sync(0xffffffffu, p2, 1);
        } else {
            #pragma unroll
            for (int off = 16; off > 0; off >>= 1) {
                p1 += __shfl_xor_sync(0xffffffffu, p1, off);
                p2 += __shfl_xor_sync(0xffffffffu, p2, off);
            }
        }
        float mp = fmaxf(p1, p2);
        if (mp > m) {
            float sc = __expf(m - mp);
            ssum *= sc;
            acc0.x *= sc; acc0.y *= sc; acc0.z *= sc; acc0.w *= sc;
            acc1.x *= sc; acc1.y *= sc; acc1.z *= sc; acc1.w *= sc;
            m = mp;
        }
        float wp = __expf(p1 - m);
        float wq = __expf(p2 - m);
        ssum += wp + wq;
        acc0.x = fmaf(wp, c0.x, fmaf(wq, d0.x, acc0.x));
        acc0.y = fmaf(wp, c0.y, fmaf(wq, d0.y, acc0.y));
        acc0.z = fmaf(wp, c0.z, fmaf(wq, d0.z, acc0.z));
        acc0.w = fmaf(wp, c0.w, fmaf(wq, d0.w, acc0.w));
        acc1.x = fmaf(wp, c1.x, fmaf(wq, d1.x, acc1.x));
        acc1.y = fmaf(wp, c1.y, fmaf(wq, d1.y, acc1.y));
        acc1.z = fmaf(wp, c1.z, fmaf(wq, d1.z, acc1.z));
        acc1.w = fmaf(wp, c1.w, fmaf(wq, d1.w, acc1.w));
    }
    if (s < s1) {   // tail edge
        float4 c0 = A0, c1 = A1;
        float p1;
        p1  =        w0.x * lrelu(c0.x + r0.x);
        p1 = fmaf(w0.y, lrelu(c0.y + r0.y), p1);
        p1 = fmaf(w0.z, lrelu(c0.z + r0.z), p1);
        p1 = fmaf(w0.w, lrelu(c0.w + r0.w), p1);
        p1 = fmaf(w1.x, lrelu(c1.x + r1.x), p1);
        p1 = fmaf(w1.y, lrelu(c1.y + r1.y), p1);
        p1 = fmaf(w1.z, lrelu(c1.z + r1.z), p1);
        p1 = fmaf(w1.w, lrelu(c1.w + r1.w), p1);
        if (LAYER == 1) {
            p1 += __shfl_xor_sync(0xffffffffu, p1, 4);
            p1 += __shfl_xor_sync(0xffffffffu, p1, 2);
            p1 += __shfl_xor_sync(0xffffffffu, p1, 1);
        } else {
            #pragma unroll
            for (int off = 16; off > 0; off >>= 1)
                p1 += __shfl_xor_sync(0xffffffffu, p1, off);
        }
        if (p1 > m) {
            float sc = __expf(m - p1);
            ssum *= sc;
            acc0.x *= sc; acc0.y *= sc; acc0.z *= sc; acc0.w *= sc;
            acc1.x *= sc; acc1.y *= sc; acc1.z *= sc; acc1.w *= sc;
            m = p1;
        }
        float wp = __expf(p1 - m);
        ssum += wp;
        acc0.x = fmaf(wp, c0.x, acc0.x); acc0.y = fmaf(wp, c0.y, acc0.y);
        acc0.z = fmaf(wp, c0.z, acc0.z); acc0.w = fmaf(wp, c0.w, acc0.w);
        acc1.x = fmaf(wp, c1.x, acc1.x); acc1.y = fmaf(wp, c1.y, acc1.y);
        acc1.z = fmaf(wp, c1.z, acc1.z); acc1.w = fmaf(wp, c1.w, acc1.w);
    }

    float inv = 1.0f / (ssum + EPSS);
    const float4* pb = (const float4*)(bias + c);
    float4 b0 = pb[0], b1 = pb[1];
    float v[8] = { acc0.x * inv + b0.x, acc0.y * inv + b0.y,
                   acc0.z * inv + b0.z, acc0.w * inv + b0.w,
                   acc1.x * inv + b1.x, acc1.y * inv + b1.y,
                   acc1.z * inv + b1.z, acc1.w * inv + b1.w };
    if (LAYER == 1) {
        #pragma unroll
        for (int j = 0; j < 8; j++) v[j] = v[j] > 0.0f ? v[j] : expm1f(v[j]);
    }
    float* outp = (LAYER == 1) ? g_h : out_arg;
    float4* po = (float4*)(outp + node * CH + c);
    po[0] = make_float4(v[0], v[1], v[2], v[3]);
    po[1] = make_float4(v[4], v[5], v[6], v[7]);
}

// ================= launcher =================================================
extern "C" void kernel_launch(void* const* d_in, const int* in_sizes, int n_in,
                              void* d_out, int out_size) {
    const float* x     = (const float*)d_in[0];
    const int*   ei    = (const int*)  d_in[1];
    const float* W_l1  = (const float*)d_in[2];
    const float* b_l1  = (const float*)d_in[3];
    const float* W_r1  = (const float*)d_in[4];
    const float* b_r1  = (const float*)d_in[5];
    const float* att1  = (const float*)d_in[6];
    const float* bias1 = (const float*)d_in[7];
    const float* W_l2  = (const float*)d_in[8];
    const float* b_l2  = (const float*)d_in[9];
    const float* W_r2  = (const float*)d_in[10];
    const float* b_r2  = (const float*)d_in[11];
    const float* att2  = (const float*)d_in[12];
    const float* bias2 = (const float*)d_in[13];
    float* out = (float*)d_out;

    const int T = 256;
    int blkN    = (NN + T - 1) / T;
    int blkE    = (ETOT + T - 1) / T;
    int blkG1   = (NN + 63) / 64;
    int blkScan = (NN + 1023) / 1024;  // 49
    int blkFe1a = (SPLIT + 7) / 8;
    int blkFe1b = (NN - SPLIT + 7) / 8;
    int blkFe2  = (NN + 7) / 8;

    // one-time side-stream + events (host resources only; no device memory)
    static cudaStream_t s2 = nullptr;
    static cudaEvent_t evFork = nullptr, evJoin = nullptr, evA = nullptr, evG = nullptr;
    if (s2 == nullptr) {
        cudaStreamCreateWithFlags(&s2, cudaStreamNonBlocking);
        cudaEventCreateWithFlags(&evFork, cudaEventDisableTiming);
        cudaEventCreateWithFlags(&evJoin, cudaEventDisableTiming);
        cudaEventCreateWithFlags(&evA, cudaEventDisableTiming);
        cudaEventCreateWithFlags(&evG, cudaEventDisableTiming);
    }

    // fork: CSR build on s2, concurrent with gemm1 on the main stream
    cudaEventRecord(evFork, 0);
    cudaStreamWaitEvent(s2, evFork, 0);

    zero_deg<<<blkN, T, 0, s2>>>();
    csr_count<<<blkE, T, 0, s2>>>(ei);
    scan1<<<blkScan, 1024, 0, s2>>>();
    scan2<<<1, 64, 0, s2>>>(blkScan);
    scan3<<<blkScan, 1024, 0, s2>>>();
    csr_scatter<<<blkE, T, 0, s2>>>(ei);
    cudaEventRecord(evJoin, s2);

    // main stream: layer-1 GEMM (independent of CSR)
    gemm1_kernel<<<blkG1, T>>>(x, W_l1, b_l1, W_r1, b_r1);

    // join: fe1 needs CSR + gemm1
    cudaStreamWaitEvent(0, evJoin, 0);

    // pipeline: fe1a -> (fe1b || gemm_a) -> gemm_b -> fe2
    fused_edge<1><<<blkFe1a, T>>>(att1, bias1, nullptr, 0, SPLIT);
    cudaEventRecord(evA, 0);
    cudaStreamWaitEvent(s2, evA, 0);
    dim3 ga(SPLIT / 128, 4);
    gemm_dual<<<ga, T, 0, s2>>>(W_l2, b_l2, W_r2, b_r2, 0);
    cudaEventRecord(evG, s2);

    fused_edge<1><<<blkFe1b, T>>>(att1, bias1, nullptr, SPLIT, NN - SPLIT);
    dim3 gb((NN - SPLIT + 127) / 128, 4);
    gemm_dual<<<gb, T>>>(W_l2, b_l2, W_r2, b_r2, SPLIT);

    cudaStreamWaitEvent(0, evG, 0);
    fused_edge<2><<<blkFe2, T>>>(att2, bias2, out, 0, NN);
}